// round 4
// baseline (speedup 1.0000x reference)
#include <cuda_runtime.h>
#include <cuda_bf16.h>

// AdEx neuron sim, sm_103a. Round 4.
// Numerics: EXACT Round-1 arithmetic (reference-ordered dv, accurate expf) —
// proven rel_err 1.6e-8 (zero spike flips). All speed comes from the non-FP side:
//  - kernel templated on N: unrolled row offsets become LDG/STG immediates
//  - guard-free steady-state loop (predicates only in epilogue)
//  - 1 neuron/thread, UNROLL=8 single-buffer in-place prefetch, ldcs/stcs

#define UNROLL 8

#define C_EL        (-70.6e-3f)
#define C_VT        (-50.4e-3f)
#define C_INVDELT   (500.0f)                 // 1 / DELTAT
#define C_GLDT      (6.0e-11f)               // GL * DELTAT
#define C_GL        (30.0e-9f)
#define C_DTCM      (3.5587188612099645e6f)  // DT / CM
#define C_DTTAUW    (6.944444444444445e-3f)  // DT / TAUW
#define C_A         (4.0e-9f)
#define C_B         (0.0805e-9f)
#define C_REFSTEPS  2

// Identical expression structure to Round 1 (do not re-associate!).
__device__ __forceinline__ void adex_step(float It, float& v, float& c, int& ref,
                                          float& v_out) {
    bool  in_ref = ref > 0;
    float v_eff  = in_ref ? C_EL : v;

    float arg = fminf((v_eff - C_VT) * C_INVDELT, 15.0f);
    float ex  = C_GLDT * expf(arg);
    float dv  = C_DTCM * (-C_GL * (v_eff - C_EL) + ex - c + It);
    float v_new = in_ref ? C_EL : (v_eff + dv);

    float c_new = c + C_DTTAUW * (C_A * (v_eff - C_EL) - c);

    bool spike = v_new >= C_VT;
    v   = spike ? C_EL : v_new;
    c   = spike ? (c_new + C_B) : c_new;
    ref = spike ? C_REFSTEPS : max(ref - 1, 0);
    v_out = v;
}

template<int N_STATIC>
__global__ void __launch_bounds__(256) adex_kernel(
    const float* __restrict__ I,    // [T, N]
    const float* __restrict__ v0,
    const float* __restrict__ c0,
    const int*   __restrict__ ref0,
    float*       __restrict__ out,  // [T, N]
    int T, int N_rt)
{
    const int N = (N_STATIC > 0) ? N_STATIC : N_rt;
    int n = blockIdx.x * blockDim.x + threadIdx.x;
    if (n >= N) return;

    float v   = v0[n];
    float c   = c0[n];
    int   ref = ref0[n];

    const float* Ip = I + n;   // row 0 base
    float*       Op = out + n;

    // prime rows 0..UNROLL-1
    float buf[UNROLL];
    #pragma unroll
    for (int u = 0; u < UNROLL; ++u)
        buf[u] = (u < T) ? __ldcs(Ip + (size_t)u * N) : 0.0f;

    // steady state: prefetch row t+UNROLL+u always valid (no predicates)
    int t = 0;
    for (; t + 2 * UNROLL <= T; t += UNROLL) {
        const float* Ipn = Ip + (size_t)(t + UNROLL) * N;  // base; +u*N are immediates
        float*       Opt = Op + (size_t)t * N;
        #pragma unroll
        for (int u = 0; u < UNROLL; ++u) {
            float It = buf[u];
            buf[u] = __ldcs(Ipn + (size_t)u * N);
            float ov;
            adex_step(It, v, c, ref, ov);
            __stcs(Opt + (size_t)u * N, ov);
        }
    }

    // epilogue 1: consume buf (rows t..t+7, all < T when T >= UNROLL),
    // refill guarded with rows t+8..T-1
    #pragma unroll
    for (int u = 0; u < UNROLL; ++u) {
        int row = t + u;
        if (row < T) {
            float It = buf[u];
            int tt = row + UNROLL;
            float nx = (tt < T) ? __ldcs(Ip + (size_t)tt * N) : 0.0f;
            float ov;
            adex_step(It, v, c, ref, ov);
            __stcs(Op + (size_t)row * N, ov);
            buf[u] = nx;
        }
    }
    t += UNROLL;

    // epilogue 2: remaining < UNROLL rows
    #pragma unroll
    for (int u = 0; u < UNROLL; ++u) {
        int row = t + u;
        if (row < T) {
            float ov;
            adex_step(buf[u], v, c, ref, ov);
            __stcs(Op + (size_t)row * N, ov);
        }
    }
}

extern "C" void kernel_launch(void* const* d_in, const int* in_sizes, int n_in,
                              void* d_out, int out_size)
{
    const float* I    = (const float*)d_in[0];
    const float* v0   = (const float*)d_in[1];
    const float* c0   = (const float*)d_in[2];
    const int*   ref0 = (const int*)  d_in[3];
    float*       out  = (float*)d_out;

    int N = in_sizes[1];
    int T = in_sizes[0] / N;

    int threads = 256;
    int blocks  = (N + threads - 1) / threads;

    if (N == 100000) {
        adex_kernel<100000><<<blocks, threads>>>(I, v0, c0, ref0, out, T, N);
    } else {
        adex_kernel<0><<<blocks, threads>>>(I, v0, c0, ref0, out, T, N);
    }
}

// round 5
// speedup vs baseline: 1.1451x; 1.1451x over previous
#include <cuda_runtime.h>
#include <cuda_bf16.h>

// AdEx neuron sim, sm_103a. Round 5.
// Round-1 reference-ordered arithmetic, with ONE localized substitution:
// expf -> __expf (ex2.approx), cutting ~12 instrs and ~30 cycles of dependent
// latency per step. UNROLL=16 single-buffer prefetch to cover DRAM latency.
// Kernel templated on N so unrolled row offsets are LDG/STG immediates.

#define UNROLL 16

#define C_EL        (-70.6e-3f)
#define C_VT        (-50.4e-3f)
#define C_INVDELT   (500.0f)                 // 1 / DELTAT
#define C_GLDT      (6.0e-11f)               // GL * DELTAT
#define C_GL        (30.0e-9f)
#define C_DTCM      (3.5587188612099645e6f)  // DT / CM
#define C_DTTAUW    (6.944444444444445e-3f)  // DT / TAUW
#define C_A         (4.0e-9f)
#define C_B         (0.0805e-9f)
#define C_REFSTEPS  2

// Reference expression structure (do not re-associate); only exp is approx.
__device__ __forceinline__ void adex_step(float It, float& v, float& c, int& ref,
                                          float& v_out) {
    bool  in_ref = ref > 0;
    float v_eff  = in_ref ? C_EL : v;

    float arg = fminf((v_eff - C_VT) * C_INVDELT, 15.0f);
    float ex  = C_GLDT * __expf(arg);        // 2-instr exp (FMUL + MUFU.EX2)
    float dv  = C_DTCM * (-C_GL * (v_eff - C_EL) + ex - c + It);
    float v_new = in_ref ? C_EL : (v_eff + dv);

    float c_new = c + C_DTTAUW * (C_A * (v_eff - C_EL) - c);

    bool spike = v_new >= C_VT;
    v   = spike ? C_EL : v_new;
    c   = spike ? (c_new + C_B) : c_new;
    ref = spike ? C_REFSTEPS : max(ref - 1, 0);
    v_out = v;
}

template<int N_STATIC>
__global__ void __launch_bounds__(256) adex_kernel(
    const float* __restrict__ I,    // [T, N]
    const float* __restrict__ v0,
    const float* __restrict__ c0,
    const int*   __restrict__ ref0,
    float*       __restrict__ out,  // [T, N]
    int T, int N_rt)
{
    const int N = (N_STATIC > 0) ? N_STATIC : N_rt;
    int n = blockIdx.x * blockDim.x + threadIdx.x;
    if (n >= N) return;

    float v   = v0[n];
    float c   = c0[n];
    int   ref = ref0[n];

    const float* Ip = I + n;
    float*       Op = out + n;

    // prime rows 0..UNROLL-1
    float buf[UNROLL];
    #pragma unroll
    for (int u = 0; u < UNROLL; ++u)
        buf[u] = (u < T) ? __ldcs(Ip + (size_t)u * N) : 0.0f;

    // steady state: prefetch row t+UNROLL+u always in range (no predicates)
    int t = 0;
    for (; t + 2 * UNROLL <= T; t += UNROLL) {
        const float* Ipn = Ip + (size_t)(t + UNROLL) * N;  // +u*N folds to immediates
        float*       Opt = Op + (size_t)t * N;
        #pragma unroll
        for (int u = 0; u < UNROLL; ++u) {
            float It = buf[u];
            buf[u] = __ldcs(Ipn + (size_t)u * N);
            float ov;
            adex_step(It, v, c, ref, ov);
            __stcs(Opt + (size_t)u * N, ov);
        }
    }

    // epilogue 1: consume resident rows t..t+UNROLL-1, refill guarded
    #pragma unroll
    for (int u = 0; u < UNROLL; ++u) {
        int row = t + u;
        if (row < T) {
            float It = buf[u];
            int tt = row + UNROLL;
            float nx = (tt < T) ? __ldcs(Ip + (size_t)tt * N) : 0.0f;
            float ov;
            adex_step(It, v, c, ref, ov);
            __stcs(Op + (size_t)row * N, ov);
            buf[u] = nx;
        }
    }
    t += UNROLL;

    // epilogue 2: remaining < UNROLL rows
    #pragma unroll
    for (int u = 0; u < UNROLL; ++u) {
        int row = t + u;
        if (row < T) {
            float ov;
            adex_step(buf[u], v, c, ref, ov);
            __stcs(Op + (size_t)row * N, ov);
        }
    }
}

extern "C" void kernel_launch(void* const* d_in, const int* in_sizes, int n_in,
                              void* d_out, int out_size)
{
    const float* I    = (const float*)d_in[0];
    const float* v0   = (const float*)d_in[1];
    const float* c0   = (const float*)d_in[2];
    const int*   ref0 = (const int*)  d_in[3];
    float*       out  = (float*)d_out;

    int N = in_sizes[1];
    int T = in_sizes[0] / N;

    int threads = 256;
    int blocks  = (N + threads - 1) / threads;

    if (N == 100000) {
        adex_kernel<100000><<<blocks, threads>>>(I, v0, c0, ref0, out, T, N);
    } else {
        adex_kernel<0><<<blocks, threads>>>(I, v0, c0, ref0, out, T, N);
    }
}